// round 14
// baseline (speedup 1.0000x reference)
#include <cuda_runtime.h>
#include <math_constants.h>

#define HFEAT 200
#define WFEAT 320
#define HWFEAT (HFEAT * WFEAT)      // 64000 pixels
#define HW4 (HWFEAT / 4)            // 16000 pixel-quads
#define CFEAT 256
#define NROI 128
#define MSZ 14
#define NBIN (MSZ * MSZ)            // 196
#define NCB 16                      // channel blocks (16 channels each)
#define CPB 16
#define NCAND (NROI * 4)            // 512 candidate points per bin
#define NSEED 8                     // rois used for seeding

// Scratch (static device arrays — no allocation)
__device__ __align__(16) float g_Mb[HWFEAT * NCB];   // [pix][cb] per-pixel 16-ch maxes (4 MB)
__device__ __align__(16) float g_best[NBIN];         // per-bin running exact max

// ---------------------------------------------------------------------------
__device__ __forceinline__ void atomicMaxFloat(float* addr, float val) {
    if (val >= 0.0f) {
        atomicMax((int*)addr, __float_as_int(val));
    } else {
        atomicMin((unsigned int*)addr, __float_as_uint(val));
    }
}

// ---------------------------------------------------------------------------
// Geometry: replicate the reference bilinear setup exactly
// (corner indices clamped FIRST, weights computed from clamped corners).
// ---------------------------------------------------------------------------
struct Geom {
    int o11, o12, o21, o22;
    float wy_lo, wy_hi, wx_lo, wx_hi;
    bool wok;   // weights form a convex combination (clamp did not trigger)
};

__device__ __forceinline__ Geom make_geom(const float* __restrict__ rois,
                                          int r, int s, int m, int n) {
    float r0 = __ldg(&rois[r * 4 + 0]);
    float r1 = __ldg(&rois[r * 4 + 1]);
    float r2 = __ldg(&rois[r * 4 + 2]);
    float r3 = __ldg(&rois[r * 4 + 3]);
    float sh = (r2 - r0) / 14.0f;
    float sw = (r3 - r1) / 14.0f;
    float fy = (s >> 1) ? (2.0f / 3.0f) : (1.0f / 3.0f);
    float fx = (s & 1)  ? (2.0f / 3.0f) : (1.0f / 3.0f);
    float y = (r0 + sh * (float)m) + sh * fy;
    float x = (r1 + sw * (float)n) + sw * fx;

    int yf = (int)floorf(y);
    int xf = (int)floorf(x);
    int y1c = min(max(yf, 0), HFEAT - 1);
    int y2c = min(max(yf + 1, 0), HFEAT - 1);
    int x1c = min(max(xf, 0), WFEAT - 1);
    int x2c = min(max(xf + 1, 0), WFEAT - 1);

    Geom g;
    g.wy_lo = y - (float)y1c;
    g.wy_hi = (float)y2c - y;
    g.wx_lo = x - (float)x1c;
    g.wx_hi = (float)x2c - x;
    g.wok = (g.wy_lo >= 0.0f) && (g.wy_lo <= 1.0f) && (g.wy_hi >= 0.0f) && (g.wy_hi <= 1.0f) &&
            (g.wx_lo >= 0.0f) && (g.wx_lo <= 1.0f) && (g.wx_hi >= 0.0f) && (g.wx_hi <= 1.0f);
    g.o11 = y1c * WFEAT + x1c;
    g.o12 = y1c * WFEAT + x2c;
    g.o21 = y2c * WFEAT + x1c;
    g.o22 = y2c * WFEAT + x2c;
    return g;
}

__device__ __forceinline__ float bilin(const float* __restrict__ base, const Geom& g) {
    float a = __ldg(base + g.o11);
    float b = __ldg(base + g.o12);
    float c = __ldg(base + g.o21);
    float d = __ldg(base + g.o22);
    return g.wy_hi * (g.wx_hi * a + g.wx_lo * b) +
           g.wy_lo * (g.wx_hi * c + g.wx_lo * d);
}

// ---------------------------------------------------------------------------
// Pass 1: per-pixel 16-channel-block maxes. (unchanged — measured good)
// grid = 1000 blocks; block = 256 threads = 16 cb x 16 pixel-quads.
// ---------------------------------------------------------------------------
__global__ void __launch_bounds__(256) k_colmax(const float4* __restrict__ f4) {
    __shared__ float s[64][NCB + 1];    // +1 pad: kill store bank conflicts

    if (blockIdx.x == 0 && threadIdx.x < NBIN)
        g_best[threadIdx.x] = -CUDART_INF_F;

    int qi = threadIdx.x & 15;          // quad within block (0..15)
    int cb = threadIdx.x >> 4;          // channel block (0..15)
    int pg = blockIdx.x * 16 + qi;      // global pixel quad (0..15999)

    const float4* p = f4 + (size_t)(cb * CPB) * HW4 + pg;
    float4 m = make_float4(-CUDART_INF_F, -CUDART_INF_F, -CUDART_INF_F, -CUDART_INF_F);
#pragma unroll
    for (int j = 0; j < CPB; j++) {
        float4 v = __ldg(p + (size_t)j * HW4);
        m.x = fmaxf(m.x, v.x); m.y = fmaxf(m.y, v.y);
        m.z = fmaxf(m.z, v.z); m.w = fmaxf(m.w, v.w);
    }
    int lpx = qi * 4;                   // local pixel 0..63
    s[lpx + 0][cb] = m.x;
    s[lpx + 1][cb] = m.y;
    s[lpx + 2][cb] = m.z;
    s[lpx + 3][cb] = m.w;
    __syncthreads();

    // write 64 px * 16 cb = 256 float4, one per thread, coalesced
    int px  = threadIdx.x >> 2;         // 0..63
    int cb0 = (threadIdx.x & 3) * 4;    // 0,4,8,12
    float4 o = make_float4(s[px][cb0], s[px][cb0 + 1], s[px][cb0 + 2], s[px][cb0 + 3]);
    float4* dst = reinterpret_cast<float4*>(g_Mb + ((size_t)blockIdx.x * 64) * NCB);
    dst[threadIdx.x] = o;
}

// ---------------------------------------------------------------------------
// Seed pass (unchanged — measured good): exact evaluation of NSEED candidate
// points per bin -> tight exact lower bounds in g_best.
// ---------------------------------------------------------------------------
__global__ void __launch_bounds__(NSEED * 32) k_seed(const float* __restrict__ f,
                                                     const float* __restrict__ rois) {
    int bin  = blockIdx.x;
    int w    = threadIdx.x >> 5;        // roi 0..NSEED-1
    int lane = threadIdx.x & 31;
    int m = bin / MSZ;
    int n = bin - m * MSZ;

    Geom g = make_geom(rois, w, 0, m, n);

    float vmax = -CUDART_INF_F;
#pragma unroll
    for (int ci = 0; ci < CFEAT / 32; ci++) {
        const float* fc = f + (size_t)(ci * 32 + lane) * HWFEAT;
        vmax = fmaxf(vmax, bilin(fc, g));
    }
#pragma unroll
    for (int o = 16; o; o >>= 1)
        vmax = fmaxf(vmax, __shfl_xor_sync(0xffffffffu, vmax, o));
    if (lane == 0) atomicMaxFloat(&g_best[bin], vmax);
}

// ---------------------------------------------------------------------------
// Screened point pass (unchanged — measured good): one warp per candidate,
// per-channel-block fine screen + per-block eval granularity.
// ---------------------------------------------------------------------------
__global__ void __launch_bounds__(256) k_points(const float* __restrict__ f,
                                                const float* __restrict__ rois) {
    int bin  = blockIdx.x;                          // 0..195
    int cand = blockIdx.y * 8 + (threadIdx.x >> 5); // 0..511
    int lane = threadIdx.x & 31;

    int r = cand >> 2;
    int s = cand & 3;
    int m = bin / MSZ;
    int n = bin - m * MSZ;

    Geom g = make_geom(rois, r, s, m, n);

    float best = __ldg(&g_best[bin]);   // seeded exact lower bound

    bool need = false;
    if (lane < NCB) {
        float m11 = __ldg(&g_Mb[(size_t)g.o11 * NCB + lane]);
        float m12 = __ldg(&g_Mb[(size_t)g.o12 * NCB + lane]);
        float m21 = __ldg(&g_Mb[(size_t)g.o21 * NCB + lane]);
        float m22 = __ldg(&g_Mb[(size_t)g.o22 * NCB + lane]);
        float ub = g.wy_hi * (g.wx_hi * m11 + g.wx_lo * m12) +
                   g.wy_lo * (g.wx_hi * m21 + g.wx_lo * m22);
        need = (!g.wok) || (ub > best);
    }
    unsigned mask = __ballot_sync(0xffffffffu, need);
    if (!mask) return;

    float vmax = -CUDART_INF_F;
    while (mask) {
        int cb0 = __ffs(mask) - 1;
        mask &= mask - 1;
        int cb1 = cb0;
        if (mask) { cb1 = __ffs(mask) - 1; mask &= mask - 1; }
        int cb = (lane < 16) ? cb0 : cb1;
        const float* fc = f + (size_t)(cb * CPB + (lane & 15)) * HWFEAT;
        vmax = fmaxf(vmax, bilin(fc, g));
    }
#pragma unroll
    for (int o = 16; o; o >>= 1)
        vmax = fmaxf(vmax, __shfl_xor_sync(0xffffffffu, vmax, o));
    if (lane == 0) atomicMaxFloat(&g_best[bin], vmax);
}

// ---------------------------------------------------------------------------
// Broadcast g_best[196] to out[R, C, 14, 14].  THE ONLY CHANGE THIS ROUND.
// Total threads 784*256 = 200704 = 49*4096: an exact multiple of the
// 49-float4 tile period. Grid-striding by exactly 200704 keeps each
// thread's tile-column index INVARIANT: compute idx once, load the float4
// into a register once, then 8 independent coalesced STG.128 — no smem,
// no __syncthreads, no per-iteration dependency chain.
// n4 = 1605632 = 8 * 200704.
// ---------------------------------------------------------------------------
__global__ void __launch_bounds__(256) k_bcast(float4* __restrict__ out) {
    int base = blockIdx.x * 256 + threadIdx.x;       // 0..200703
    int idx  = base % (NBIN / 4);                    // invariant under +200704
    float4 val = __ldg(&reinterpret_cast<const float4*>(g_best)[idx]);
#pragma unroll
    for (int k = 0; k < 8; k++)
        out[base + k * 200704] = val;
}

// ---------------------------------------------------------------------------
extern "C" void kernel_launch(void* const* d_in, const int* in_sizes, int n_in,
                              void* d_out, int out_size) {
    const float* feature = (const float*)d_in[0];   // [1,256,200,320] f32
    const float* rois    = (const float*)d_in[1];   // [128,4] f32
    float* out           = (float*)d_out;           // [128,256,14,14] f32

    // Pass 1: per-pixel 16-channel block maxes (+ g_best init)
    k_colmax<<<HW4 / 16, 256>>>((const float4*)feature);

    // Seed: exact per-bin lower bounds from 8 candidates
    k_seed<<<NBIN, NSEED * 32>>>(feature, rois);

    // Screened pass over all (bin, candidate) pairs
    dim3 g2(NBIN, NCAND / 8);
    k_points<<<g2, 256>>>(feature, rois);

    // Broadcast result (register-resident value, 8 independent stores/thread)
    k_bcast<<<784, 256>>>((float4*)out);
}